// round 5
// baseline (speedup 1.0000x reference)
#include <cuda_runtime.h>
#include <math.h>

#define N_NODES  50000
#define N_EDGES  800000
#define NF       64
#define N_GRAPHS 512

// ---------------- scratch (no allocations allowed) ----------------
__device__ __align__(16) float g_h[N_NODES * NF];    // GEMM output, pre-scaled by dinv[row]
__device__ __align__(16) float g_out[N_NODES * NF];  // aggregation output / next-layer input
__device__ float g_dinv[N_NODES];
__device__ int   g_deg[N_NODES];
__device__ float g_pool[N_GRAPHS];
__device__ float g_cnt[N_GRAPHS];

// ---------------- init / degree ----------------
__global__ void k_zero() {
    int i = blockIdx.x * blockDim.x + threadIdx.x;
    if (i < N_NODES) g_deg[i] = 0;
    if (i < N_GRAPHS) { g_pool[i] = 0.f; g_cnt[i] = 0.f; }
}

__global__ void k_deg(const int* __restrict__ dst) {
    int e = blockIdx.x * blockDim.x + threadIdx.x;
    if (e < N_EDGES) atomicAdd(&g_deg[dst[e]], 1);
}

__global__ void k_cnt(const int* __restrict__ batch) {
    int i = blockIdx.x * blockDim.x + threadIdx.x;
    if (i < N_NODES) atomicAdd(&g_cnt[batch[i]], 1.0f);
}

__global__ void k_dinv() {
    int i = blockIdx.x * blockDim.x + threadIdx.x;
    if (i < N_NODES) g_dinv[i] = rsqrtf((float)(g_deg[i] + 1));  // +1 self-loop
}

// ---------------- GEMM: Hs[i][:] = dinv[i] * (relu?(src[i][:]) @ W) ----------------
// FROM_SCRATCH: read the previous layer's output from the device global g_out
// (device-side reference only — passing a __device__ symbol from host code
// passes the host shadow address, which is wrong).
template <bool RELU, bool FROM_SCRATCH>
__global__ void k_gemm(const float* __restrict__ X, const float* __restrict__ W) {
    __shared__ float Ws[64 * 64];
    int tid = threadIdx.x;
    for (int i = tid; i < 4096; i += 256) Ws[i] = W[i];
    __syncthreads();

    int warp = tid >> 5, lane = tid & 31;
#pragma unroll 1
    for (int it = 0; it < 8; ++it) {
        int row = blockIdx.x * 64 + it * 8 + warp;
        if (row >= N_NODES) break;
        const float* xr = (FROM_SCRATCH ? g_out : X) + (size_t)row * 64;
        float xlo = xr[lane], xhi = xr[lane + 32];
        if (RELU) { xlo = fmaxf(xlo, 0.f); xhi = fmaxf(xhi, 0.f); }
        float a0 = 0.f, a1 = 0.f;
#pragma unroll
        for (int k = 0; k < 32; ++k) {
            float xk = __shfl_sync(0xffffffffu, xlo, k);
            a0 = fmaf(xk, Ws[k * 64 + lane], a0);
            a1 = fmaf(xk, Ws[k * 64 + lane + 32], a1);
        }
#pragma unroll
        for (int k = 0; k < 32; ++k) {
            float xk = __shfl_sync(0xffffffffu, xhi, k);
            a0 = fmaf(xk, Ws[(k + 32) * 64 + lane], a0);
            a1 = fmaf(xk, Ws[(k + 32) * 64 + lane + 32], a1);
        }
        float dv = g_dinv[row];
        g_h[(size_t)row * 64 + lane]      = a0 * dv;
        g_h[(size_t)row * 64 + lane + 32] = a1 * dv;
    }
}

// ---------------- out[i][:] = b[:] + dinv[i] * Hs[i][:]  (self-loop + bias) ----------------
__global__ void k_init(const float* __restrict__ b) {
    int idx = blockIdx.x * blockDim.x + threadIdx.x;  // N_NODES*16 float4 chunks
    if (idx >= N_NODES * 16) return;
    int node = idx >> 4, sub = idx & 15;
    float dv = g_dinv[node];
    float4 h = reinterpret_cast<const float4*>(g_h)[idx];
    float4 bb = reinterpret_cast<const float4*>(b)[sub];
    float4 o;
    o.x = fmaf(dv, h.x, bb.x);
    o.y = fmaf(dv, h.y, bb.y);
    o.z = fmaf(dv, h.z, bb.z);
    o.w = fmaf(dv, h.w, bb.w);
    reinterpret_cast<float4*>(g_out)[idx] = o;
}

// ---------------- edge scatter: out[dst] += Hs[src] * dinv[dst] ----------------
__global__ void k_edge(const int* __restrict__ src, const int* __restrict__ dst) {
    int idx = blockIdx.x * blockDim.x + threadIdx.x;  // N_EDGES*16 = 12.8M threads
    if (idx >= N_EDGES * 16) return;
    int e = idx >> 4, sub = idx & 15;
    int s = src[e];
    int d = dst[e];
    float nd = g_dinv[d];
    float4 v = reinterpret_cast<const float4*>(g_h)[s * 16 + sub];
    v.x *= nd; v.y *= nd; v.z *= nd; v.w *= nd;
    float4* p = reinterpret_cast<float4*>(g_out) + d * 16 + sub;
    asm volatile("red.global.add.v4.f32 [%0], {%1, %2, %3, %4};"
                 :: "l"(p), "f"(v.x), "f"(v.y), "f"(v.z), "f"(v.w)
                 : "memory");
}

// ---------------- pooling fused with classifier dot: pool[g] += dot(h3[i], Wl) ----------------
__global__ void k_pool(const int* __restrict__ batch, const float* __restrict__ Wl) {
    int gidx = blockIdx.x * blockDim.x + threadIdx.x;
    int node = gidx >> 5, lane = gidx & 31;
    if (node >= N_NODES) return;
    const float* hr = g_out + (size_t)node * 64;
    float v = hr[lane] * Wl[lane] + hr[lane + 32] * Wl[lane + 32];
#pragma unroll
    for (int off = 16; off > 0; off >>= 1)
        v += __shfl_down_sync(0xffffffffu, v, off);
    if (lane == 0) atomicAdd(&g_pool[batch[node]], v);
}

__global__ void k_final(const float* __restrict__ bl, float* __restrict__ out) {
    int g = blockIdx.x * blockDim.x + threadIdx.x;
    if (g >= N_GRAPHS) return;
    float c = fmaxf(g_cnt[g], 1.0f);
    float z = g_pool[g] / c + bl[0];
    out[g] = 1.0f / (1.0f + expf(-z));
}

// ---------------- static-init warmup ----------------
// Forces context creation, module load (materializes the __device__ globals),
// per-function lazy load, and launch-resource pools before main(). Uses only
// device addresses obtained via cudaGetSymbolAddress. All state touched here
// is fully recomputed by every real kernel_launch call.
namespace {
struct CudaWarmup {
    CudaWarmup() {
        cudaFree(0);
        void *ph = nullptr, *pout = nullptr, *pdeg = nullptr;
        cudaGetSymbolAddress(&ph,   g_h);
        cudaGetSymbolAddress(&pout, g_out);
        cudaGetSymbolAddress(&pdeg, g_deg);
        const float* fh = (const float*)ph;
        const int*   id = (const int*)pdeg;   // zero-initialized -> index 0, safe
        k_zero<<<1, 32>>>();
        k_deg<<<1, 32>>>(id);
        k_cnt<<<1, 32>>>(id);
        k_dinv<<<1, 32>>>();
        k_gemm<false, false><<<1, 256>>>(fh, fh);
        k_gemm<true,  true ><<<1, 256>>>(nullptr, fh);
        k_init<<<1, 256>>>(fh);
        k_edge<<<1, 256>>>(id, id);
        k_pool<<<1, 256>>>(id, fh);
        k_final<<<1, 32>>>(fh, (float*)pout);
        cudaDeviceSynchronize();
    }
};
CudaWarmup g_warmup_instance;
}  // namespace

// ---------------- launch ----------------
extern "C" void kernel_launch(void* const* d_in, const int* in_sizes, int n_in,
                              void* d_out, int out_size) {
    const float* x     = (const float*)d_in[0];
    const int*   ei    = (const int*)d_in[1];    // int32 (JAX x64 disabled)
    const int*   batch = (const int*)d_in[2];
    const float* W1 = (const float*)d_in[3];
    const float* b1 = (const float*)d_in[4];
    const float* W2 = (const float*)d_in[5];
    const float* b2 = (const float*)d_in[6];
    const float* W3 = (const float*)d_in[7];
    const float* b3 = (const float*)d_in[8];
    const float* Wl = (const float*)d_in[9];
    const float* bl = (const float*)d_in[10];
    float* out = (float*)d_out;

    const int* srcp = ei;
    const int* dstp = ei + N_EDGES;

    const int TPB = 256;
    const int nodeBlocks  = (N_NODES + TPB - 1) / TPB;          // 196
    const int edgeBlocks  = (N_EDGES + TPB - 1) / TPB;          // 3125
    const int gemmBlocks  = (N_NODES + 63) / 64;                // 782
    const int initBlocks  = (N_NODES * 16 + TPB - 1) / TPB;     // 3125
    const int scatBlocks  = (N_EDGES * 16 + TPB - 1) / TPB;     // 50000
    const int poolBlocks  = (N_NODES * 32 + TPB - 1) / TPB;     // 6250

    k_zero<<<nodeBlocks, TPB>>>();
    k_deg<<<edgeBlocks, TPB>>>(dstp);
    k_cnt<<<nodeBlocks, TPB>>>(batch);
    k_dinv<<<nodeBlocks, TPB>>>();

    // layer 1 (reads harness input x)
    k_gemm<false, false><<<gemmBlocks, TPB>>>(x, W1);
    k_init<<<initBlocks, TPB>>>(b1);
    k_edge<<<scatBlocks, TPB>>>(srcp, dstp);

    // layer 2 (reads g_out device-side; relu fused into gemm read)
    k_gemm<true, true><<<gemmBlocks, TPB>>>(nullptr, W2);
    k_init<<<initBlocks, TPB>>>(b2);
    k_edge<<<scatBlocks, TPB>>>(srcp, dstp);

    // layer 3
    k_gemm<true, true><<<gemmBlocks, TPB>>>(nullptr, W3);
    k_init<<<initBlocks, TPB>>>(b3);
    k_edge<<<scatBlocks, TPB>>>(srcp, dstp);

    // mean-pool + linear head + sigmoid
    k_pool<<<poolBlocks, TPB>>>(batch, Wl);
    k_final<<<(N_GRAPHS + TPB - 1) / TPB, TPB>>>(bl, out);
}

// round 6
// speedup vs baseline: 1.3306x; 1.3306x over previous
#include <cuda_runtime.h>
#include <math.h>

#define N_NODES  50000
#define N_EDGES  800000
#define N_GRAPHS 512

// ---------------- scratch (no allocations allowed) ----------------
__device__ __align__(16) float g_h[N_NODES * 64];    // hs = dinv[row] * (in @ W); gather source
__device__ __align__(16) float g_acc[N_NODES * 64];  // aggregation accumulator (init = hs self term)
__device__ int   g_deg[N_NODES];
__device__ float g_pool[N_GRAPHS];
__device__ float g_cnt[N_GRAPHS];

// ---------------- setup: zero deg/pool + graph counts via binary search ----------------
__global__ void k_setup(const int* __restrict__ batch) {
    int i = blockIdx.x * blockDim.x + threadIdx.x;
    if (i < N_NODES) g_deg[i] = 0;
    if (i < N_GRAPHS) {
        g_pool[i] = 0.f;
        // batch is sorted ascending: cnt[i] = upper_bound(i) - lower_bound(i)
        int a = 0, b = N_NODES;
        while (a < b) { int m = (a + b) >> 1; if (batch[m] < i) a = m + 1; else b = m; }
        int lb = a;
        a = 0; b = N_NODES;
        while (a < b) { int m = (a + b) >> 1; if (batch[m] <= i) a = m + 1; else b = m; }
        g_cnt[i] = (float)(a - lb);
    }
}

__global__ void k_deg(const int* __restrict__ dst) {
    int e = blockIdx.x * blockDim.x + threadIdx.x;
    if (e < N_EDGES) atomicAdd(&g_deg[dst[e]], 1);
}

// ---------------- GEMM + fused prev-layer epilogue ----------------
// LAYER==0 : input row j = X[row][j]
// LAYER>0  : input row j = relu(bprev[j] + dv_row * g_acc[row][j])   (prev layer's output)
// Output   : hs = dv_row * (input @ W), written to BOTH g_h and g_acc (self-loop init).
// 8 warps/block, each warp processes 8 rows in 2 groups of 4; one smem weight
// load feeds 4 rows' FMAs (4x less smem traffic than 1-row-per-warp).
template <int LAYER>
__global__ void k_gemm(const float* __restrict__ X, const float* __restrict__ W,
                       const float* __restrict__ bprev) {
    __shared__ float Ws[64 * 64];
    int tid = threadIdx.x;
    for (int i = tid; i < 4096; i += 256) Ws[i] = W[i];
    __syncthreads();

    int warp = tid >> 5, lane = tid & 31;
    float blo = 0.f, bhi = 0.f;
    if (LAYER > 0) { blo = bprev[lane]; bhi = bprev[lane + 32]; }

#pragma unroll
    for (int grp = 0; grp < 2; ++grp) {
        int r0 = blockIdx.x * 64 + warp * 8 + grp * 4;
        if (r0 >= N_NODES) break;
        int nv = N_NODES - r0; if (nv > 4) nv = 4;

        float xl[4], xh[4], dvr[4];
#pragma unroll
        for (int i = 0; i < 4; ++i) {
            xl[i] = 0.f; xh[i] = 0.f; dvr[i] = 0.f;
            if (i < nv) {
                int row = r0 + i;
                dvr[i] = rsqrtf((float)(g_deg[row] + 1));
                if (LAYER == 0) {
                    const float* xr = X + (size_t)row * 64;
                    xl[i] = xr[lane]; xh[i] = xr[lane + 32];
                } else {
                    const float* ar = g_acc + (size_t)row * 64;
                    xl[i] = fmaxf(fmaf(dvr[i], ar[lane],      blo), 0.f);
                    xh[i] = fmaxf(fmaf(dvr[i], ar[lane + 32], bhi), 0.f);
                }
            }
        }

        float a0[4] = {0.f, 0.f, 0.f, 0.f}, a1[4] = {0.f, 0.f, 0.f, 0.f};
#pragma unroll 8
        for (int k = 0; k < 32; ++k) {
            float w0 = Ws[k * 64 + lane], w1 = Ws[k * 64 + lane + 32];
#pragma unroll
            for (int i = 0; i < 4; ++i) {
                float xk = __shfl_sync(0xffffffffu, xl[i], k);
                a0[i] = fmaf(xk, w0, a0[i]);
                a1[i] = fmaf(xk, w1, a1[i]);
            }
        }
#pragma unroll 8
        for (int k = 0; k < 32; ++k) {
            float w0 = Ws[(k + 32) * 64 + lane], w1 = Ws[(k + 32) * 64 + lane + 32];
#pragma unroll
            for (int i = 0; i < 4; ++i) {
                float xk = __shfl_sync(0xffffffffu, xh[i], k);
                a0[i] = fmaf(xk, w0, a0[i]);
                a1[i] = fmaf(xk, w1, a1[i]);
            }
        }

#pragma unroll
        for (int i = 0; i < 4; ++i) {
            if (i < nv) {
                int row = r0 + i;
                float v0 = a0[i] * dvr[i], v1 = a1[i] * dvr[i];
                g_h[(size_t)row * 64 + lane]        = v0;
                g_h[(size_t)row * 64 + lane + 32]   = v1;
                g_acc[(size_t)row * 64 + lane]      = v0;
                g_acc[(size_t)row * 64 + lane + 32] = v1;
            }
        }
    }
}

// ---------------- edge scatter: acc[dst] += hs[src] (pure gather + red.v4) ----------------
__global__ void k_edge(const int* __restrict__ src, const int* __restrict__ dst) {
    int idx = blockIdx.x * blockDim.x + threadIdx.x;  // N_EDGES*16 lanes
    if (idx >= N_EDGES * 16) return;
    int e = idx >> 4, sub = idx & 15;
    int s = src[e];
    int d = dst[e];
    float4 v = reinterpret_cast<const float4*>(g_h)[s * 16 + sub];
    float4* p = reinterpret_cast<float4*>(g_acc) + d * 16 + sub;
    asm volatile("red.global.add.v4.f32 [%0], {%1, %2, %3, %4};"
                 :: "l"(p), "f"(v.x), "f"(v.y), "f"(v.z), "f"(v.w)
                 : "memory");
}

// ---------------- pool: layer-3 epilogue + classifier dot, fused ----------------
// h3[j] = b3[j] + dv*acc3[j];  pool[batch] += dot(h3, Wl)
__global__ void k_pool(const int* __restrict__ batch, const float* __restrict__ Wl,
                       const float* __restrict__ b3) {
    int gidx = blockIdx.x * blockDim.x + threadIdx.x;
    int node = gidx >> 5, lane = gidx & 31;
    if (node >= N_NODES) return;
    float dv = rsqrtf((float)(g_deg[node] + 1));
    const float* ar = g_acc + (size_t)node * 64;
    float v = fmaf(dv, ar[lane],      b3[lane])      * Wl[lane]
            + fmaf(dv, ar[lane + 32], b3[lane + 32]) * Wl[lane + 32];
#pragma unroll
    for (int off = 16; off > 0; off >>= 1)
        v += __shfl_down_sync(0xffffffffu, v, off);
    if (lane == 0) atomicAdd(&g_pool[batch[node]], v);
}

__global__ void k_final(const float* __restrict__ bl, float* __restrict__ out) {
    int g = blockIdx.x * blockDim.x + threadIdx.x;
    if (g >= N_GRAPHS) return;
    float c = fmaxf(g_cnt[g], 1.0f);
    float z = g_pool[g] / c + bl[0];
    out[g] = 1.0f / (1.0f + expf(-z));
}

// ---------------- static-init warmup (context/module/lazy-load before harness baseline) ----------------
namespace {
struct CudaWarmup {
    CudaWarmup() {
        cudaFree(0);
        void *ph = nullptr, *pout = nullptr, *pdeg = nullptr;
        cudaGetSymbolAddress(&ph,   g_h);
        cudaGetSymbolAddress(&pout, g_acc);
        cudaGetSymbolAddress(&pdeg, g_deg);
        const float* fh = (const float*)ph;
        const int*   id = (const int*)pdeg;   // zero-initialized -> safe indices/values
        k_setup<<<1, 32>>>(id);               // batch=zeros (sorted), fine
        k_deg<<<1, 32>>>(id);
        k_gemm<0><<<1, 256>>>(fh, fh, fh);
        k_gemm<1><<<1, 256>>>(nullptr, fh, fh);
        k_gemm<2><<<1, 256>>>(nullptr, fh, fh);
        k_edge<<<1, 256>>>(id, id);
        k_pool<<<1, 256>>>(id, fh, fh);
        k_final<<<1, 32>>>(fh, (float*)pout);
        cudaDeviceSynchronize();
    }
};
CudaWarmup g_warmup_instance;
}  // namespace

// ---------------- launch ----------------
extern "C" void kernel_launch(void* const* d_in, const int* in_sizes, int n_in,
                              void* d_out, int out_size) {
    const float* x     = (const float*)d_in[0];
    const int*   ei    = (const int*)d_in[1];    // int32 (JAX x64 disabled)
    const int*   batch = (const int*)d_in[2];
    const float* W1 = (const float*)d_in[3];
    const float* b1 = (const float*)d_in[4];
    const float* W2 = (const float*)d_in[5];
    const float* b2 = (const float*)d_in[6];
    const float* W3 = (const float*)d_in[7];
    const float* b3 = (const float*)d_in[8];
    const float* Wl = (const float*)d_in[9];
    const float* bl = (const float*)d_in[10];
    float* out = (float*)d_out;

    const int* srcp = ei;
    const int* dstp = ei + N_EDGES;

    const int TPB = 256;
    const int nodeBlocks = (N_NODES + TPB - 1) / TPB;        // 196
    const int edgeBlocks = (N_EDGES + TPB - 1) / TPB;        // 3125
    const int gemmBlocks = (N_NODES + 63) / 64;              // 782
    const int scatBlocks = (N_EDGES * 16 + TPB - 1) / TPB;   // 50000
    const int poolBlocks = (N_NODES * 32 + TPB - 1) / TPB;   // 6250

    k_setup<<<nodeBlocks, TPB>>>(batch);
    k_deg<<<edgeBlocks, TPB>>>(dstp);

    // layer 1
    k_gemm<0><<<gemmBlocks, TPB>>>(x, W1, nullptr);
    k_edge<<<scatBlocks, TPB>>>(srcp, dstp);
    // layer 2 (epilogue of layer 1 fused into read)
    k_gemm<1><<<gemmBlocks, TPB>>>(nullptr, W2, b1);
    k_edge<<<scatBlocks, TPB>>>(srcp, dstp);
    // layer 3
    k_gemm<2><<<gemmBlocks, TPB>>>(nullptr, W3, b2);
    k_edge<<<scatBlocks, TPB>>>(srcp, dstp);

    // layer-3 epilogue + mean-pool + linear head + sigmoid
    k_pool<<<poolBlocks, TPB>>>(batch, Wl, b3);
    k_final<<<(N_GRAPHS + TPB - 1) / TPB, TPB>>>(bl, out);
}

// round 7
// speedup vs baseline: 1.4036x; 1.0549x over previous
#include <cuda_runtime.h>
#include <math.h>

#define N_NODES  50000
#define N_EDGES  800000
#define N_GRAPHS 512

// ---------------- scratch (no allocations allowed) ----------------
__device__ __align__(16) float g_h[N_NODES * 64];    // hs = dinv[row] * (in @ W); gather source
__device__ __align__(16) float g_acc[N_NODES * 64];  // aggregation result
__device__ int   g_deg[N_NODES];     // in-degree (without self loop)
__device__ int   g_start[N_NODES];   // CSR row starts (exclusive scan of deg)
__device__ int   g_fill[N_NODES];    // CSR fill cursors
__device__ int   g_csr[N_EDGES];     // src indices grouped by dst
__device__ float g_pool[N_GRAPHS];
__device__ float g_cnt[N_GRAPHS];

// ---------------- setup: zero deg/fill/pool + graph counts via binary search ----------------
__global__ void k_setup(const int* __restrict__ batch) {
    int i = blockIdx.x * blockDim.x + threadIdx.x;
    if (i < N_NODES) { g_deg[i] = 0; g_fill[i] = 0; }
    if (i < N_GRAPHS) {
        g_pool[i] = 0.f;
        // batch sorted ascending: cnt[i] = upper_bound(i) - lower_bound(i)
        int a = 0, b = N_NODES;
        while (a < b) { int m = (a + b) >> 1; if (batch[m] < i) a = m + 1; else b = m; }
        int lb = a;
        a = 0; b = N_NODES;
        while (a < b) { int m = (a + b) >> 1; if (batch[m] <= i) a = m + 1; else b = m; }
        g_cnt[i] = (float)(a - lb);
    }
}

__global__ void k_deg(const int* __restrict__ dst) {
    int e = blockIdx.x * blockDim.x + threadIdx.x;
    if (e < N_EDGES) atomicAdd(&g_deg[dst[e]], 1);
}

// ---------------- single-block exclusive scan of g_deg -> g_start ----------------
// Launch with exactly 1024 threads. Each thread serially sums ~49 elements,
// block-scans the 1024 partial sums, then writes its exclusive positions.
__global__ void k_scan() {
    __shared__ int ssum[1024];
    int t = threadIdx.x;
    const int PER = (N_NODES + 1023) / 1024;  // 49
    int lo = t * PER, hi = lo + PER; if (hi > N_NODES) hi = N_NODES;
    int sum = 0;
    for (int i = lo; i < hi; i++) sum += g_deg[i];
    ssum[t] = sum;
    __syncthreads();
    for (int off = 1; off < 1024; off <<= 1) {
        int v = (t >= off) ? ssum[t - off] : 0;
        __syncthreads();
        ssum[t] += v;
        __syncthreads();
    }
    int run = (t == 0) ? 0 : ssum[t - 1];
    for (int i = lo; i < hi; i++) { g_start[i] = run; run += g_deg[i]; }
}

// ---------------- CSR fill: slot src into dst's adjacency list ----------------
__global__ void k_fill(const int* __restrict__ src, const int* __restrict__ dst) {
    int e = blockIdx.x * blockDim.x + threadIdx.x;
    if (e >= N_EDGES) return;
    int d = dst[e];
    int pos = g_start[d] + atomicAdd(&g_fill[d], 1);
    g_csr[pos] = src[e];
}

// ---------------- GEMM + fused prev-layer epilogue ----------------
// LAYER==0 : input row j = X[row][j]
// LAYER>0  : input row j = relu(bprev[j] + dv_row * g_acc[row][j])
// Output   : g_h = dv_row * (input @ W)
template <int LAYER>
__global__ void k_gemm(const float* __restrict__ X, const float* __restrict__ W,
                       const float* __restrict__ bprev) {
    __shared__ float Ws[64 * 64];
    int tid = threadIdx.x;
    for (int i = tid; i < 4096; i += 256) Ws[i] = W[i];
    __syncthreads();

    int warp = tid >> 5, lane = tid & 31;
    float blo = 0.f, bhi = 0.f;
    if (LAYER > 0) { blo = bprev[lane]; bhi = bprev[lane + 32]; }

#pragma unroll
    for (int grp = 0; grp < 2; ++grp) {
        int r0 = blockIdx.x * 64 + warp * 8 + grp * 4;
        if (r0 >= N_NODES) break;
        int nv = N_NODES - r0; if (nv > 4) nv = 4;

        float xl[4], xh[4], dvr[4];
#pragma unroll
        for (int i = 0; i < 4; ++i) {
            xl[i] = 0.f; xh[i] = 0.f; dvr[i] = 0.f;
            if (i < nv) {
                int row = r0 + i;
                dvr[i] = rsqrtf((float)(g_deg[row] + 1));
                if (LAYER == 0) {
                    const float* xr = X + (size_t)row * 64;
                    xl[i] = xr[lane]; xh[i] = xr[lane + 32];
                } else {
                    const float* ar = g_acc + (size_t)row * 64;
                    xl[i] = fmaxf(fmaf(dvr[i], ar[lane],      blo), 0.f);
                    xh[i] = fmaxf(fmaf(dvr[i], ar[lane + 32], bhi), 0.f);
                }
            }
        }

        float a0[4] = {0.f, 0.f, 0.f, 0.f}, a1[4] = {0.f, 0.f, 0.f, 0.f};
#pragma unroll 8
        for (int k = 0; k < 32; ++k) {
            float w0 = Ws[k * 64 + lane], w1 = Ws[k * 64 + lane + 32];
#pragma unroll
            for (int i = 0; i < 4; ++i) {
                float xk = __shfl_sync(0xffffffffu, xl[i], k);
                a0[i] = fmaf(xk, w0, a0[i]);
                a1[i] = fmaf(xk, w1, a1[i]);
            }
        }
#pragma unroll 8
        for (int k = 0; k < 32; ++k) {
            float w0 = Ws[(k + 32) * 64 + lane], w1 = Ws[(k + 32) * 64 + lane + 32];
#pragma unroll
            for (int i = 0; i < 4; ++i) {
                float xk = __shfl_sync(0xffffffffu, xh[i], k);
                a0[i] = fmaf(xk, w0, a0[i]);
                a1[i] = fmaf(xk, w1, a1[i]);
            }
        }

#pragma unroll
        for (int i = 0; i < 4; ++i) {
            if (i < nv) {
                int row = r0 + i;
                g_h[(size_t)row * 64 + lane]      = a0[i] * dvr[i];
                g_h[(size_t)row * 64 + lane + 32] = a1[i] * dvr[i];
            }
        }
    }
}

// ---------------- CSR aggregation: acc[d] = hs[d] + sum_{s in N(d)} hs[s] ----------------
// One warp per dst node; lane owns 2 floats (float2). Neighbor indices loaded
// warp-wide (1 LDG per 32 neighbors) and broadcast by shuffle. No atomics.
__global__ void k_aggr() {
    int warp_id = (blockIdx.x * blockDim.x + threadIdx.x) >> 5;
    int lane = threadIdx.x & 31;
    if (warp_id >= N_NODES) return;
    int node = warp_id;

    const float2* h2 = reinterpret_cast<const float2*>(g_h);
    float2 acc = h2[node * 32 + lane];  // self-loop term

    int beg = g_start[node];
    int end = beg + g_deg[node];
    for (int chunk = beg; chunk < end; chunk += 32) {
        int myidx = chunk + lane;
        int s = (myidx < end) ? g_csr[myidx] : 0;
        int n = end - chunk; if (n > 32) n = 32;
        for (int j = 0; j < n; ++j) {
            int sj = __shfl_sync(0xffffffffu, s, j);
            float2 v = h2[sj * 32 + lane];
            acc.x += v.x; acc.y += v.y;
        }
    }
    reinterpret_cast<float2*>(g_acc)[node * 32 + lane] = acc;
}

// ---------------- pool: layer-3 epilogue + classifier dot, fused ----------------
__global__ void k_pool(const int* __restrict__ batch, const float* __restrict__ Wl,
                       const float* __restrict__ b3) {
    int gidx = blockIdx.x * blockDim.x + threadIdx.x;
    int node = gidx >> 5, lane = gidx & 31;
    if (node >= N_NODES) return;
    float dv = rsqrtf((float)(g_deg[node] + 1));
    const float* ar = g_acc + (size_t)node * 64;
    float v = fmaf(dv, ar[lane],      b3[lane])      * Wl[lane]
            + fmaf(dv, ar[lane + 32], b3[lane + 32]) * Wl[lane + 32];
#pragma unroll
    for (int off = 16; off > 0; off >>= 1)
        v += __shfl_down_sync(0xffffffffu, v, off);
    if (lane == 0) atomicAdd(&g_pool[batch[node]], v);
}

__global__ void k_final(const float* __restrict__ bl, float* __restrict__ out) {
    int g = blockIdx.x * blockDim.x + threadIdx.x;
    if (g >= N_GRAPHS) return;
    float c = fmaxf(g_cnt[g], 1.0f);
    float z = g_pool[g] / c + bl[0];
    out[g] = 1.0f / (1.0f + expf(-z));
}

// ---------------- static-init warmup (context/module/lazy-load before harness baseline) ----------------
namespace {
struct CudaWarmup {
    CudaWarmup() {
        cudaFree(0);
        void *ph = nullptr, *pout = nullptr, *pdeg = nullptr;
        cudaGetSymbolAddress(&ph,   g_h);
        cudaGetSymbolAddress(&pout, g_acc);
        cudaGetSymbolAddress(&pdeg, g_deg);
        const float* fh = (const float*)ph;
        const int*   id = (const int*)pdeg;   // zero-initialized -> safe indices/values
        k_setup<<<1, 32>>>(id);
        k_deg<<<1, 32>>>(id);
        k_scan<<<1, 1024>>>();
        k_fill<<<1, 32>>>(id, id);
        k_gemm<0><<<1, 256>>>(fh, fh, fh);
        k_gemm<1><<<1, 256>>>(nullptr, fh, fh);
        k_gemm<2><<<1, 256>>>(nullptr, fh, fh);
        k_aggr<<<1, 256>>>();
        k_pool<<<1, 256>>>(id, fh, fh);
        k_final<<<1, 32>>>(fh, (float*)pout);
        cudaDeviceSynchronize();
    }
};
CudaWarmup g_warmup_instance;
}  // namespace

// ---------------- launch ----------------
extern "C" void kernel_launch(void* const* d_in, const int* in_sizes, int n_in,
                              void* d_out, int out_size) {
    const float* x     = (const float*)d_in[0];
    const int*   ei    = (const int*)d_in[1];    // int32 (JAX x64 disabled)
    const int*   batch = (const int*)d_in[2];
    const float* W1 = (const float*)d_in[3];
    const float* b1 = (const float*)d_in[4];
    const float* W2 = (const float*)d_in[5];
    const float* b2 = (const float*)d_in[6];
    const float* W3 = (const float*)d_in[7];
    const float* b3 = (const float*)d_in[8];
    const float* Wl = (const float*)d_in[9];
    const float* bl = (const float*)d_in[10];
    float* out = (float*)d_out;

    const int* srcp = ei;
    const int* dstp = ei + N_EDGES;

    const int TPB = 256;
    const int nodeBlocks = (N_NODES + TPB - 1) / TPB;            // 196
    const int edgeBlocks = (N_EDGES + TPB - 1) / TPB;            // 3125
    const int gemmBlocks = (N_NODES + 63) / 64;                  // 782
    const int aggrBlocks = (N_NODES * 32 + TPB - 1) / TPB;       // 6250 (warp/node)
    const int poolBlocks = (N_NODES * 32 + TPB - 1) / TPB;       // 6250

    // CSR build (per launch; graph static within a call)
    k_setup<<<nodeBlocks, TPB>>>(batch);
    k_deg<<<edgeBlocks, TPB>>>(dstp);
    k_scan<<<1, 1024>>>();
    k_fill<<<edgeBlocks, TPB>>>(srcp, dstp);

    // layer 1
    k_gemm<0><<<gemmBlocks, TPB>>>(x, W1, nullptr);
    k_aggr<<<aggrBlocks, TPB>>>();
    // layer 2 (layer-1 epilogue fused into read)
    k_gemm<1><<<gemmBlocks, TPB>>>(nullptr, W2, b1);
    k_aggr<<<aggrBlocks, TPB>>>();
    // layer 3
    k_gemm<2><<<gemmBlocks, TPB>>>(nullptr, W3, b2);
    k_aggr<<<aggrBlocks, TPB>>>();

    // layer-3 epilogue + mean-pool + linear head + sigmoid
    k_pool<<<poolBlocks, TPB>>>(batch, Wl, b3);
    k_final<<<(N_GRAPHS + TPB - 1) / TPB, TPB>>>(bl, out);
}

// round 8
// speedup vs baseline: 1.4497x; 1.0329x over previous
#include <cuda_runtime.h>
#include <cuda_fp16.h>
#include <math.h>

#define N_NODES  50000
#define N_EDGES  800000
#define N_GRAPHS 512

// ---------------- scratch (no allocations allowed) ----------------
// g_h layout: row-major, 32 half2 per row; slot j = (feat j, feat j+32)
__device__ __align__(16) __half2 g_h[N_NODES * 32];
// g_acc layout: 32 float2 per row; slot j = (feat j, feat j+32)
__device__ __align__(16) float2 g_acc[N_NODES * 32];
__device__ int   g_deg[N_NODES];     // in-degree (without self loop)
__device__ int   g_start[N_NODES];   // CSR row starts
__device__ int   g_fill[N_NODES];    // CSR fill cursors
__device__ int   g_csr[N_EDGES];     // src indices grouped by dst
__device__ float g_pool[N_GRAPHS];
__device__ float g_cnt[N_GRAPHS];

// ---------------- setup: zero deg/fill/pool + graph counts via binary search ----------------
__global__ void k_setup(const int* __restrict__ batch) {
    int i = blockIdx.x * blockDim.x + threadIdx.x;
    if (i < N_NODES) { g_deg[i] = 0; g_fill[i] = 0; }
    if (i < N_GRAPHS) {
        g_pool[i] = 0.f;
        int a = 0, b = N_NODES;
        while (a < b) { int m = (a + b) >> 1; if (batch[m] < i) a = m + 1; else b = m; }
        int lb = a;
        a = 0; b = N_NODES;
        while (a < b) { int m = (a + b) >> 1; if (batch[m] <= i) a = m + 1; else b = m; }
        g_cnt[i] = (float)(a - lb);
    }
}

__global__ void k_deg(const int* __restrict__ dst) {
    int e = blockIdx.x * blockDim.x + threadIdx.x;
    if (e < N_EDGES) atomicAdd(&g_deg[dst[e]], 1);
}

// ---------------- single-block exclusive scan of g_deg -> g_start ----------------
__global__ void k_scan() {
    __shared__ int ssum[1024];
    int t = threadIdx.x;
    const int PER = (N_NODES + 1023) / 1024;  // 49
    int lo = t * PER, hi = lo + PER; if (hi > N_NODES) hi = N_NODES;
    int sum = 0;
    for (int i = lo; i < hi; i++) sum += g_deg[i];
    ssum[t] = sum;
    __syncthreads();
    for (int off = 1; off < 1024; off <<= 1) {
        int v = (t >= off) ? ssum[t - off] : 0;
        __syncthreads();
        ssum[t] += v;
        __syncthreads();
    }
    int run = (t == 0) ? 0 : ssum[t - 1];
    for (int i = lo; i < hi; i++) { g_start[i] = run; run += g_deg[i]; }
}

__global__ void k_fill(const int* __restrict__ src, const int* __restrict__ dst) {
    int e = blockIdx.x * blockDim.x + threadIdx.x;
    if (e >= N_EDGES) return;
    int d = dst[e];
    int pos = g_start[d] + atomicAdd(&g_fill[d], 1);
    g_csr[pos] = src[e];
}

// ---------------- GEMM + fused prev-layer epilogue ----------------
// LAYER==0 : input row j = X[row][j] (fp32, natural layout)
// LAYER>0  : input = relu(bprev + dv * g_acc[row]) where g_acc slot lane = (f_lane, f_lane+32)
// Output   : g_h[row] slot lane = half2(dv*(in@W)[lane], dv*(in@W)[lane+32])
template <int LAYER>
__global__ void k_gemm(const float* __restrict__ X, const float* __restrict__ W,
                       const float* __restrict__ bprev) {
    __shared__ float Ws[64 * 64];
    int tid = threadIdx.x;
    for (int i = tid; i < 4096; i += 256) Ws[i] = W[i];
    __syncthreads();

    int warp = tid >> 5, lane = tid & 31;
    float blo = 0.f, bhi = 0.f;
    if (LAYER > 0) { blo = bprev[lane]; bhi = bprev[lane + 32]; }

#pragma unroll
    for (int grp = 0; grp < 2; ++grp) {
        int r0 = blockIdx.x * 64 + warp * 8 + grp * 4;
        if (r0 >= N_NODES) break;
        int nv = N_NODES - r0; if (nv > 4) nv = 4;

        float xl[4], xh[4], dvr[4];
#pragma unroll
        for (int i = 0; i < 4; ++i) {
            xl[i] = 0.f; xh[i] = 0.f; dvr[i] = 0.f;
            if (i < nv) {
                int row = r0 + i;
                dvr[i] = rsqrtf((float)(g_deg[row] + 1));
                if (LAYER == 0) {
                    const float* xr = X + (size_t)row * 64;
                    xl[i] = xr[lane]; xh[i] = xr[lane + 32];
                } else {
                    float2 a = g_acc[row * 32 + lane];
                    xl[i] = fmaxf(fmaf(dvr[i], a.x, blo), 0.f);
                    xh[i] = fmaxf(fmaf(dvr[i], a.y, bhi), 0.f);
                }
            }
        }

        float a0[4] = {0.f, 0.f, 0.f, 0.f}, a1[4] = {0.f, 0.f, 0.f, 0.f};
#pragma unroll 8
        for (int k = 0; k < 32; ++k) {
            float w0 = Ws[k * 64 + lane], w1 = Ws[k * 64 + lane + 32];
#pragma unroll
            for (int i = 0; i < 4; ++i) {
                float xk = __shfl_sync(0xffffffffu, xl[i], k);
                a0[i] = fmaf(xk, w0, a0[i]);
                a1[i] = fmaf(xk, w1, a1[i]);
            }
        }
#pragma unroll 8
        for (int k = 0; k < 32; ++k) {
            float w0 = Ws[(k + 32) * 64 + lane], w1 = Ws[(k + 32) * 64 + lane + 32];
#pragma unroll
            for (int i = 0; i < 4; ++i) {
                float xk = __shfl_sync(0xffffffffu, xh[i], k);
                a0[i] = fmaf(xk, w0, a0[i]);
                a1[i] = fmaf(xk, w1, a1[i]);
            }
        }

#pragma unroll
        for (int i = 0; i < 4; ++i) {
            if (i < nv) {
                int row = r0 + i;
                g_h[row * 32 + lane] = __floats2half2_rn(a0[i] * dvr[i], a1[i] * dvr[i]);
            }
        }
    }
}

// ---------------- CSR aggregation: acc[d] = hs[d] + sum_{s in N(d)} hs[s] ----------------
// One warp per dst node; lane owns half2 slot lane (128 B/row = 1 cache line).
// Neighbor indices loaded warp-wide, broadcast via shuffle; inner loop unrolled
// x4 for MLP. Accumulation in fp32.
// FINAL: apply layer-3 epilogue (b3 + dv*acc), dot with Wl, atomicAdd to pool.
template <bool FINAL>
__global__ void k_aggr(const int* __restrict__ batch, const float* __restrict__ Wl,
                       const float* __restrict__ b3) {
    int warp_id = (blockIdx.x * blockDim.x + threadIdx.x) >> 5;
    int lane = threadIdx.x & 31;
    if (warp_id >= N_NODES) return;
    int node = warp_id;

    float2 self = __half22float2(g_h[node * 32 + lane]);
    float ax = self.x, ay = self.y;

    int beg = g_start[node];
    int deg = g_deg[node];
    int end = beg + deg;
    for (int chunk = beg; chunk < end; chunk += 32) {
        int myidx = chunk + lane;
        int s = (myidx < end) ? g_csr[myidx] : 0;
        int n = end - chunk; if (n > 32) n = 32;
        int j = 0;
        for (; j + 4 <= n; j += 4) {
            int s0 = __shfl_sync(0xffffffffu, s, j);
            int s1 = __shfl_sync(0xffffffffu, s, j + 1);
            int s2 = __shfl_sync(0xffffffffu, s, j + 2);
            int s3 = __shfl_sync(0xffffffffu, s, j + 3);
            __half2 v0 = g_h[s0 * 32 + lane];
            __half2 v1 = g_h[s1 * 32 + lane];
            __half2 v2 = g_h[s2 * 32 + lane];
            __half2 v3 = g_h[s3 * 32 + lane];
            float2 f0 = __half22float2(v0), f1 = __half22float2(v1);
            float2 f2 = __half22float2(v2), f3 = __half22float2(v3);
            ax += (f0.x + f1.x) + (f2.x + f3.x);
            ay += (f0.y + f1.y) + (f2.y + f3.y);
        }
        for (; j < n; ++j) {
            int sj = __shfl_sync(0xffffffffu, s, j);
            float2 f = __half22float2(g_h[sj * 32 + lane]);
            ax += f.x; ay += f.y;
        }
    }

    if (!FINAL) {
        g_acc[node * 32 + lane] = make_float2(ax, ay);
    } else {
        float dv = rsqrtf((float)(deg + 1));
        float v = fmaf(dv, ax, b3[lane])      * Wl[lane]
                + fmaf(dv, ay, b3[lane + 32]) * Wl[lane + 32];
#pragma unroll
        for (int off = 16; off > 0; off >>= 1)
            v += __shfl_down_sync(0xffffffffu, v, off);
        if (lane == 0) atomicAdd(&g_pool[batch[node]], v);
    }
}

__global__ void k_final(const float* __restrict__ bl, float* __restrict__ out) {
    int g = blockIdx.x * blockDim.x + threadIdx.x;
    if (g >= N_GRAPHS) return;
    float c = fmaxf(g_cnt[g], 1.0f);
    float z = g_pool[g] / c + bl[0];
    out[g] = 1.0f / (1.0f + expf(-z));
}

// ---------------- static-init warmup (context/module/lazy-load before harness baseline) ----------------
namespace {
struct CudaWarmup {
    CudaWarmup() {
        cudaFree(0);
        void *ph = nullptr, *pout = nullptr, *pdeg = nullptr;
        cudaGetSymbolAddress(&ph,   g_h);
        cudaGetSymbolAddress(&pout, g_acc);
        cudaGetSymbolAddress(&pdeg, g_deg);
        const float* fh = (const float*)ph;
        const int*   id = (const int*)pdeg;   // zero-initialized -> safe indices/values
        k_setup<<<1, 32>>>(id);
        k_deg<<<1, 32>>>(id);
        k_scan<<<1, 1024>>>();
        k_fill<<<1, 32>>>(id, id);
        k_gemm<0><<<1, 256>>>(fh, fh, fh);
        k_gemm<1><<<1, 256>>>(nullptr, fh, fh);
        k_gemm<2><<<1, 256>>>(nullptr, fh, fh);
        k_aggr<false><<<1, 256>>>(id, fh, fh);
        k_aggr<true><<<1, 256>>>(id, fh, fh);
        k_final<<<1, 32>>>(fh, (float*)pout);
        cudaDeviceSynchronize();
    }
};
CudaWarmup g_warmup_instance;
}  // namespace

// ---------------- launch ----------------
extern "C" void kernel_launch(void* const* d_in, const int* in_sizes, int n_in,
                              void* d_out, int out_size) {
    const float* x     = (const float*)d_in[0];
    const int*   ei    = (const int*)d_in[1];    // int32 (JAX x64 disabled)
    const int*   batch = (const int*)d_in[2];
    const float* W1 = (const float*)d_in[3];
    const float* b1 = (const float*)d_in[4];
    const float* W2 = (const float*)d_in[5];
    const float* b2 = (const float*)d_in[6];
    const float* W3 = (const float*)d_in[7];
    const float* b3 = (const float*)d_in[8];
    const float* Wl = (const float*)d_in[9];
    const float* bl = (const float*)d_in[10];
    float* out = (float*)d_out;

    const int* srcp = ei;
    const int* dstp = ei + N_EDGES;

    const int TPB = 256;
    const int nodeBlocks = (N_NODES + TPB - 1) / TPB;            // 196
    const int edgeBlocks = (N_EDGES + TPB - 1) / TPB;            // 3125
    const int gemmBlocks = (N_NODES + 63) / 64;                  // 782
    const int aggrBlocks = (N_NODES * 32 + TPB - 1) / TPB;       // 6250 (warp/node)

    // CSR build (per launch; graph static within a call)
    k_setup<<<nodeBlocks, TPB>>>(batch);
    k_deg<<<edgeBlocks, TPB>>>(dstp);
    k_scan<<<1, 1024>>>();
    k_fill<<<edgeBlocks, TPB>>>(srcp, dstp);

    // layer 1
    k_gemm<0><<<gemmBlocks, TPB>>>(x, W1, nullptr);
    k_aggr<false><<<aggrBlocks, TPB>>>(nullptr, nullptr, nullptr);
    // layer 2 (layer-1 epilogue fused into read)
    k_gemm<1><<<gemmBlocks, TPB>>>(nullptr, W2, b1);
    k_aggr<false><<<aggrBlocks, TPB>>>(nullptr, nullptr, nullptr);
    // layer 3 + fused epilogue/pool
    k_gemm<2><<<gemmBlocks, TPB>>>(nullptr, W3, b2);
    k_aggr<true><<<aggrBlocks, TPB>>>(batch, Wl, b3);

    // mean + linear head + sigmoid
    k_final<<<(N_GRAPHS + TPB - 1) / TPB, TPB>>>(bl, out);
}

// round 9
// speedup vs baseline: 1.8540x; 1.2789x over previous
#include <cuda_runtime.h>
#include <cuda_fp16.h>
#include <math.h>

#define N_NODES  50000
#define N_EDGES  800000
#define N_GRAPHS 512

// ---------------- scratch (no allocations allowed) ----------------
// g_h: 32 half2 per row; slot j = feats (2j, 2j+1)
__device__ __align__(16) __half2 g_h[N_NODES * 32];
// g_acc: 32 float2 per row; slot j = feats (2j, 2j+1)
__device__ __align__(16) float2 g_acc[N_NODES * 32];
__device__ int   g_deg[N_NODES];
__device__ int   g_start[N_NODES];
__device__ int   g_fill[N_NODES];
__device__ int   g_csr[N_EDGES];
__device__ float g_pool[N_GRAPHS];
__device__ float g_cnt[N_GRAPHS];

// ---------------- setup: zero deg/fill/pool + graph counts via binary search ----------------
__global__ void k_setup(const int* __restrict__ batch) {
    int i = blockIdx.x * blockDim.x + threadIdx.x;
    if (i < N_NODES) { g_deg[i] = 0; g_fill[i] = 0; }
    if (i < N_GRAPHS) {
        g_pool[i] = 0.f;
        int a = 0, b = N_NODES;
        while (a < b) { int m = (a + b) >> 1; if (batch[m] < i) a = m + 1; else b = m; }
        int lb = a;
        a = 0; b = N_NODES;
        while (a < b) { int m = (a + b) >> 1; if (batch[m] <= i) a = m + 1; else b = m; }
        g_cnt[i] = (float)(a - lb);
    }
}

__global__ void k_deg(const int* __restrict__ dst) {
    int e = blockIdx.x * blockDim.x + threadIdx.x;
    if (e < N_EDGES) atomicAdd(&g_deg[dst[e]], 1);
}

// ---------------- single-block exclusive scan of g_deg -> g_start ----------------
__global__ void k_scan() {
    __shared__ int ssum[1024];
    int t = threadIdx.x;
    const int PER = (N_NODES + 1023) / 1024;  // 49
    int lo = t * PER, hi = lo + PER; if (hi > N_NODES) hi = N_NODES;
    int sum = 0;
    for (int i = lo; i < hi; i++) sum += g_deg[i];
    ssum[t] = sum;
    __syncthreads();
    for (int off = 1; off < 1024; off <<= 1) {
        int v = (t >= off) ? ssum[t - off] : 0;
        __syncthreads();
        ssum[t] += v;
        __syncthreads();
    }
    int run = (t == 0) ? 0 : ssum[t - 1];
    for (int i = lo; i < hi; i++) { g_start[i] = run; run += g_deg[i]; }
}

__global__ void k_fill(const int* __restrict__ src, const int* __restrict__ dst) {
    int e = blockIdx.x * blockDim.x + threadIdx.x;
    if (e >= N_EDGES) return;
    int d = dst[e];
    int pos = g_start[d] + atomicAdd(&g_fill[d], 1);
    g_csr[pos] = src[e];
}

// ---------------- register-tiled GEMM + fused prev-layer epilogue ----------------
// Block = 64 rows x 64 cols, 256 threads, thread computes 4x4.
// LAYER==0: input = X (fp32 natural layout)
// LAYER>0 : input = relu(bprev + dv*g_acc), g_acc slot s = feats (2s,2s+1)
// Output  : g_h[row] slot j = half2(dv*y[2j], dv*y[2j+1])
template <int LAYER>
__global__ __launch_bounds__(256) void k_gemm(const float* __restrict__ X,
                                              const float* __restrict__ W,
                                              const float* __restrict__ bprev) {
    __shared__ float Xs[64][68];
    __shared__ float Ws[64][68];
    __shared__ float sdv[64];
    int tid = threadIdx.x;
    int base = blockIdx.x * 64;

    if (tid < 64) {
        int row = base + tid;
        sdv[tid] = (row < N_NODES) ? rsqrtf((float)(g_deg[row] + 1)) : 0.f;
    }
#pragma unroll
    for (int i = 0; i < 4; ++i) {           // W tile: 1024 float4
        int idx = tid + i * 256;
        int k = idx >> 4, cc = (idx & 15) << 2;
        float4 w = *(const float4*)(W + k * 64 + cc);
        Ws[k][cc] = w.x; Ws[k][cc + 1] = w.y; Ws[k][cc + 2] = w.z; Ws[k][cc + 3] = w.w;
    }
    __syncthreads();                        // sdv ready for LAYER>0 load

    if (LAYER == 0) {
#pragma unroll
        for (int i = 0; i < 4; ++i) {
            int idx = tid + i * 256;
            int row = idx >> 4, kc = (idx & 15) << 2;
            int grow = base + row;
            float4 v = make_float4(0.f, 0.f, 0.f, 0.f);
            if (grow < N_NODES) v = *(const float4*)(X + (size_t)grow * 64 + kc);
            Xs[row][kc] = v.x; Xs[row][kc + 1] = v.y; Xs[row][kc + 2] = v.z; Xs[row][kc + 3] = v.w;
        }
    } else {
#pragma unroll
        for (int i = 0; i < 8; ++i) {
            int idx = tid + i * 256;        // 2048 slots = 64 rows x 32
            int row = idx >> 5, s = idx & 31;
            int grow = base + row;
            float x0 = 0.f, x1 = 0.f;
            if (grow < N_NODES) {
                float2 a = g_acc[grow * 32 + s];
                float dv = sdv[row];
                x0 = fmaxf(fmaf(dv, a.x, bprev[2 * s]),     0.f);
                x1 = fmaxf(fmaf(dv, a.y, bprev[2 * s + 1]), 0.f);
            }
            Xs[row][2 * s] = x0; Xs[row][2 * s + 1] = x1;
        }
    }
    __syncthreads();

    int ty = tid >> 4, tx = tid & 15;
    int r0 = ty * 4, c0 = tx * 4;
    float acc[4][4] = {};
#pragma unroll 2
    for (int k4 = 0; k4 < 64; k4 += 4) {
        float xr[4][4], wr[4][4];
#pragma unroll
        for (int i = 0; i < 4; ++i) {
            float4 v = *(const float4*)&Xs[r0 + i][k4];
            xr[i][0] = v.x; xr[i][1] = v.y; xr[i][2] = v.z; xr[i][3] = v.w;
        }
#pragma unroll
        for (int kk = 0; kk < 4; ++kk) {
            float4 v = *(const float4*)&Ws[k4 + kk][c0];
            wr[kk][0] = v.x; wr[kk][1] = v.y; wr[kk][2] = v.z; wr[kk][3] = v.w;
        }
#pragma unroll
        for (int kk = 0; kk < 4; ++kk)
#pragma unroll
            for (int i = 0; i < 4; ++i)
#pragma unroll
                for (int j = 0; j < 4; ++j)
                    acc[i][j] = fmaf(xr[i][kk], wr[kk][j], acc[i][j]);
    }

#pragma unroll
    for (int i = 0; i < 4; ++i) {
        int grow = base + r0 + i;
        if (grow < N_NODES) {
            float dv = sdv[r0 + i];
            __half2 h0 = __floats2half2_rn(acc[i][0] * dv, acc[i][1] * dv);
            __half2 h1 = __floats2half2_rn(acc[i][2] * dv, acc[i][3] * dv);
            unsigned u0 = *reinterpret_cast<unsigned*>(&h0);
            unsigned u1 = *reinterpret_cast<unsigned*>(&h1);
            *reinterpret_cast<uint2*>(&g_h[grow * 32 + 2 * tx]) = make_uint2(u0, u1);
        }
    }
}

// ---------------- CSR aggregation: acc[d] = hs[d] + sum_{s in N(d)} hs[s] ----------------
// Warp per node; lane owns half2 slot. Neighbor indices warp-loaded + shuffled;
// x8 unroll for MLP. fp32 accumulate.
// FINAL: layer-3 epilogue + classifier dot + pool atomicAdd (slot = feats 2l,2l+1).
template <bool FINAL>
__global__ void k_aggr(const int* __restrict__ batch, const float* __restrict__ Wl,
                       const float* __restrict__ b3) {
    int warp_id = (blockIdx.x * blockDim.x + threadIdx.x) >> 5;
    int lane = threadIdx.x & 31;
    if (warp_id >= N_NODES) return;
    int node = warp_id;

    float2 self = __half22float2(g_h[node * 32 + lane]);
    float ax = self.x, ay = self.y;

    int beg = g_start[node];
    int deg = g_deg[node];
    int end = beg + deg;
    for (int chunk = beg; chunk < end; chunk += 32) {
        int myidx = chunk + lane;
        int s = (myidx < end) ? g_csr[myidx] : 0;
        int n = end - chunk; if (n > 32) n = 32;
        int j = 0;
        for (; j + 8 <= n; j += 8) {
            int si[8];
#pragma unroll
            for (int u = 0; u < 8; ++u) si[u] = __shfl_sync(0xffffffffu, s, j + u);
            float2 f[8];
#pragma unroll
            for (int u = 0; u < 8; ++u) f[u] = __half22float2(g_h[si[u] * 32 + lane]);
#pragma unroll
            for (int u = 0; u < 8; ++u) { ax += f[u].x; ay += f[u].y; }
        }
        for (; j < n; ++j) {
            int sj = __shfl_sync(0xffffffffu, s, j);
            float2 f = __half22float2(g_h[sj * 32 + lane]);
            ax += f.x; ay += f.y;
        }
    }

    if (!FINAL) {
        g_acc[node * 32 + lane] = make_float2(ax, ay);
    } else {
        float dv = rsqrtf((float)(deg + 1));
        float v = fmaf(dv, ax, b3[2 * lane])     * Wl[2 * lane]
                + fmaf(dv, ay, b3[2 * lane + 1]) * Wl[2 * lane + 1];
#pragma unroll
        for (int off = 16; off > 0; off >>= 1)
            v += __shfl_down_sync(0xffffffffu, v, off);
        if (lane == 0) atomicAdd(&g_pool[batch[node]], v);
    }
}

__global__ void k_final(const float* __restrict__ bl, float* __restrict__ out) {
    int g = blockIdx.x * blockDim.x + threadIdx.x;
    if (g >= N_GRAPHS) return;
    float c = fmaxf(g_cnt[g], 1.0f);
    float z = g_pool[g] / c + bl[0];
    out[g] = 1.0f / (1.0f + expf(-z));
}

// ---------------- static-init warmup + stream/event creation ----------------
namespace {
cudaStream_t g_side;
cudaEvent_t  g_ev0, g_ev1;
struct CudaWarmup {
    CudaWarmup() {
        cudaFree(0);
        cudaStreamCreateWithFlags(&g_side, cudaStreamNonBlocking);
        cudaEventCreateWithFlags(&g_ev0, cudaEventDisableTiming);
        cudaEventCreateWithFlags(&g_ev1, cudaEventDisableTiming);
        void *ph = nullptr, *pout = nullptr, *pdeg = nullptr;
        cudaGetSymbolAddress(&ph,   g_h);
        cudaGetSymbolAddress(&pout, g_acc);
        cudaGetSymbolAddress(&pdeg, g_deg);
        const float* fh = (const float*)ph;
        const int*   id = (const int*)pdeg;   // zero-initialized -> safe indices/values
        k_setup<<<1, 32>>>(id);
        k_deg<<<1, 32>>>(id);
        cudaEventRecord(g_ev0, 0);
        cudaStreamWaitEvent(g_side, g_ev0, 0);
        k_scan<<<1, 1024, 0, g_side>>>();
        k_fill<<<1, 32, 0, g_side>>>(id, id);
        cudaEventRecord(g_ev1, g_side);
        cudaStreamWaitEvent(0, g_ev1, 0);
        k_gemm<0><<<1, 256>>>(fh, fh, fh);
        k_gemm<1><<<1, 256>>>(nullptr, fh, fh);
        k_gemm<2><<<1, 256>>>(nullptr, fh, fh);
        k_aggr<false><<<1, 256>>>(id, fh, fh);
        k_aggr<true><<<1, 256>>>(id, fh, fh);
        k_final<<<1, 32>>>(fh, (float*)pout);
        cudaDeviceSynchronize();
    }
};
CudaWarmup g_warmup_instance;
}  // namespace

// ---------------- launch ----------------
extern "C" void kernel_launch(void* const* d_in, const int* in_sizes, int n_in,
                              void* d_out, int out_size) {
    const float* x     = (const float*)d_in[0];
    const int*   ei    = (const int*)d_in[1];    // int32 (JAX x64 disabled)
    const int*   batch = (const int*)d_in[2];
    const float* W1 = (const float*)d_in[3];
    const float* b1 = (const float*)d_in[4];
    const float* W2 = (const float*)d_in[5];
    const float* b2 = (const float*)d_in[6];
    const float* W3 = (const float*)d_in[7];
    const float* b3 = (const float*)d_in[8];
    const float* Wl = (const float*)d_in[9];
    const float* bl = (const float*)d_in[10];
    float* out = (float*)d_out;

    const int* srcp = ei;
    const int* dstp = ei + N_EDGES;

    const int TPB = 256;
    const int nodeBlocks = (N_NODES + TPB - 1) / TPB;        // 196
    const int edgeBlocks = (N_EDGES + TPB - 1) / TPB;        // 3125
    const int gemmBlocks = (N_NODES + 63) / 64;              // 782
    const int aggrBlocks = (N_NODES * 32 + TPB - 1) / TPB;   // 6250 (warp/node)

    // degree (needed by both CSR build and GEMM's dinv)
    k_setup<<<nodeBlocks, TPB>>>(batch);
    k_deg<<<edgeBlocks, TPB>>>(dstp);

    // fork: CSR scan+fill on side stream, overlapped with layer-1 GEMM
    cudaEventRecord(g_ev0, 0);
    cudaStreamWaitEvent(g_side, g_ev0, 0);
    k_scan<<<1, 1024, 0, g_side>>>();
    k_fill<<<edgeBlocks, TPB, 0, g_side>>>(srcp, dstp);
    cudaEventRecord(g_ev1, g_side);

    k_gemm<0><<<gemmBlocks, TPB>>>(x, W1, nullptr);
    cudaStreamWaitEvent(0, g_ev1, 0);    // join before first aggregation

    k_aggr<false><<<aggrBlocks, TPB>>>(nullptr, nullptr, nullptr);
    k_gemm<1><<<gemmBlocks, TPB>>>(nullptr, W2, b1);
    k_aggr<false><<<aggrBlocks, TPB>>>(nullptr, nullptr, nullptr);
    k_gemm<2><<<gemmBlocks, TPB>>>(nullptr, W3, b2);
    k_aggr<true><<<aggrBlocks, TPB>>>(batch, Wl, b3);

    k_final<<<(N_GRAPHS + TPB - 1) / TPB, TPB>>>(bl, out);
}

// round 10
// speedup vs baseline: 1.9123x; 1.0314x over previous
#include <cuda_runtime.h>
#include <cuda_fp16.h>
#include <math.h>

#define N_NODES  50000
#define N_EDGES  800000
#define N_GRAPHS 512
#define TPB      256
#define N_TILES  ((N_NODES + 63) / 64)

// ---------------- scratch (no allocations allowed) ----------------
// g_h: 32 half2 per row; slot j = feats (2j, 2j+1)
__device__ __align__(16) __half2 g_h[N_NODES * 32];
// g_acc: 32 float2 per row; slot j = feats (2j, 2j+1)
__device__ __align__(16) float2 g_acc[N_NODES * 32];
__device__ int   g_deg[N_NODES];
__device__ int   g_start[N_NODES];
__device__ int   g_fill[N_NODES];
__device__ int   g_csr[N_EDGES];
__device__ float g_pool[N_GRAPHS];
__device__ float g_cnt[N_GRAPHS];
__device__ int   g_total;
__device__ unsigned g_bar_count;
__device__ volatile unsigned g_bar_gen;

// ---------------- shared-memory union (one 35KB pool for all phases) ----------------
union SmemU {
    struct { float Xs[64][68]; float Ws[64][68]; float sdv[64]; } gemm;
    struct { int vals[TPB]; int carry; } scan;
};

// ---------------- software grid barrier (grid sized to full co-residency) ----------------
__device__ __forceinline__ void gbar() {
    __syncthreads();
    if (threadIdx.x == 0) {
        __threadfence();
        unsigned gen = g_bar_gen;
        unsigned arrived = atomicAdd(&g_bar_count, 1u) + 1u;
        if (arrived == gridDim.x) {
            g_bar_count = 0u;
            __threadfence();
            g_bar_gen = gen + 1u;
        } else {
            while (g_bar_gen == gen) { __nanosleep(64); }
        }
        __threadfence();
    }
    __syncthreads();
}

// ---------------- GEMM phase: g_h = dv * (input @ W), input fused from prev layer ----------------
template <int LAYER>
__device__ __forceinline__ void gemm_phase(SmemU& sm, const float* __restrict__ X,
                                           const float* __restrict__ W,
                                           const float* __restrict__ bprev) {
    const int tid = threadIdx.x;
    __syncthreads();  // smem union handoff
#pragma unroll
    for (int i = 0; i < 4; ++i) {
        int idx = tid + i * 256;
        int k = idx >> 4, cc = (idx & 15) << 2;
        *(float4*)&sm.gemm.Ws[k][cc] = *(const float4*)(W + k * 64 + cc);
    }
    __syncthreads();

    const int ty = tid >> 4, tx = tid & 15;
    const int r0 = ty * 4, c0 = tx * 4;

    for (int t = blockIdx.x; t < N_TILES; t += gridDim.x) {
        int base = t * 64;
        if (tid < 64) {
            int row = base + tid;
            sm.gemm.sdv[tid] = (row < N_NODES) ? rsqrtf((float)(g_deg[row] + 1)) : 0.f;
        }
        __syncthreads();

        if (LAYER == 0) {
#pragma unroll
            for (int i = 0; i < 4; ++i) {
                int idx = tid + i * 256;
                int row = idx >> 4, kc = (idx & 15) << 2;
                int grow = base + row;
                float4 v = make_float4(0.f, 0.f, 0.f, 0.f);
                if (grow < N_NODES) v = *(const float4*)(X + (size_t)grow * 64 + kc);
                *(float4*)&sm.gemm.Xs[row][kc] = v;
            }
        } else {
#pragma unroll
            for (int i = 0; i < 8; ++i) {
                int idx = tid + i * 256;       // 2048 = 64 rows x 32 slots
                int row = idx >> 5, s = idx & 31;
                int grow = base + row;
                float x0 = 0.f, x1 = 0.f;
                if (grow < N_NODES) {
                    float2 a = g_acc[grow * 32 + s];
                    float dv = sm.gemm.sdv[row];
                    x0 = fmaxf(fmaf(dv, a.x, bprev[2 * s]),     0.f);
                    x1 = fmaxf(fmaf(dv, a.y, bprev[2 * s + 1]), 0.f);
                }
                sm.gemm.Xs[row][2 * s] = x0;
                sm.gemm.Xs[row][2 * s + 1] = x1;
            }
        }
        __syncthreads();

        float acc[4][4] = {};
#pragma unroll 2
        for (int k4 = 0; k4 < 64; k4 += 4) {
            float xr[4][4], wr[4][4];
#pragma unroll
            for (int i = 0; i < 4; ++i) {
                float4 v = *(const float4*)&sm.gemm.Xs[r0 + i][k4];
                xr[i][0] = v.x; xr[i][1] = v.y; xr[i][2] = v.z; xr[i][3] = v.w;
            }
#pragma unroll
            for (int kk = 0; kk < 4; ++kk) {
                float4 v = *(const float4*)&sm.gemm.Ws[k4 + kk][c0];
                wr[kk][0] = v.x; wr[kk][1] = v.y; wr[kk][2] = v.z; wr[kk][3] = v.w;
            }
#pragma unroll
            for (int kk = 0; kk < 4; ++kk)
#pragma unroll
                for (int i = 0; i < 4; ++i)
#pragma unroll
                    for (int j = 0; j < 4; ++j)
                        acc[i][j] = fmaf(xr[i][kk], wr[kk][j], acc[i][j]);
        }

#pragma unroll
        for (int i = 0; i < 4; ++i) {
            int grow = base + r0 + i;
            if (grow < N_NODES) {
                float dv = sm.gemm.sdv[r0 + i];
                __half2 h0 = __floats2half2_rn(acc[i][0] * dv, acc[i][1] * dv);
                __half2 h1 = __floats2half2_rn(acc[i][2] * dv, acc[i][3] * dv);
                unsigned u0 = *reinterpret_cast<unsigned*>(&h0);
                unsigned u1 = *reinterpret_cast<unsigned*>(&h1);
                *reinterpret_cast<uint2*>(&g_h[grow * 32 + 2 * tx]) = make_uint2(u0, u1);
            }
        }
        __syncthreads();  // protect Xs/sdv before next tile
    }
}

// ---------------- aggregation phase: acc[d] = hs[d] + sum_{s in N(d)} hs[s] ----------------
template <bool FINAL>
__device__ __forceinline__ void aggr_phase(const int* __restrict__ batch,
                                           const float* __restrict__ Wl,
                                           const float* __restrict__ b3) {
    int lane = threadIdx.x & 31;
    int wid = (blockIdx.x * blockDim.x + threadIdx.x) >> 5;
    int nw = (gridDim.x * blockDim.x) >> 5;

    for (int node = wid; node < N_NODES; node += nw) {
        float2 self = __half22float2(g_h[node * 32 + lane]);
        float ax = self.x, ay = self.y;

        int beg = g_start[node];
        int deg = g_deg[node];
        int end = beg + deg;
        for (int chunk = beg; chunk < end; chunk += 32) {
            int myidx = chunk + lane;
            int s = (myidx < end) ? g_csr[myidx] : 0;
            int n = end - chunk; if (n > 32) n = 32;
            int j = 0;
            for (; j + 8 <= n; j += 8) {
                int si[8];
#pragma unroll
                for (int u = 0; u < 8; ++u) si[u] = __shfl_sync(0xffffffffu, s, j + u);
                float2 f[8];
#pragma unroll
                for (int u = 0; u < 8; ++u) f[u] = __half22float2(g_h[si[u] * 32 + lane]);
#pragma unroll
                for (int u = 0; u < 8; ++u) { ax += f[u].x; ay += f[u].y; }
            }
            for (; j < n; ++j) {
                int sj = __shfl_sync(0xffffffffu, s, j);
                float2 f = __half22float2(g_h[sj * 32 + lane]);
                ax += f.x; ay += f.y;
            }
        }

        if (!FINAL) {
            g_acc[node * 32 + lane] = make_float2(ax, ay);
        } else {
            float dv = rsqrtf((float)(deg + 1));
            float v = fmaf(dv, ax, b3[2 * lane])     * Wl[2 * lane]
                    + fmaf(dv, ay, b3[2 * lane + 1]) * Wl[2 * lane + 1];
#pragma unroll
            for (int off = 16; off > 0; off >>= 1)
                v += __shfl_down_sync(0xffffffffu, v, off);
            if (lane == 0) atomicAdd(&g_pool[batch[node]], v);
        }
    }
}

// ---------------- the single persistent kernel ----------------
__global__ __launch_bounds__(TPB) void k_persist(
    const float* __restrict__ x, const int* __restrict__ src, const int* __restrict__ dst,
    const int* __restrict__ batch,
    const float* __restrict__ W1, const float* __restrict__ b1,
    const float* __restrict__ W2, const float* __restrict__ b2,
    const float* __restrict__ W3, const float* __restrict__ b3,
    const float* __restrict__ Wl, const float* __restrict__ bl,
    float* __restrict__ out)
{
    __shared__ SmemU sm;
    const int tid = threadIdx.x;
    const int gtid = blockIdx.x * TPB + tid;
    const int nthr = gridDim.x * TPB;

    // ---- P0: zero deg/fill/pool/total + per-graph counts (batch sorted -> binsearch) ----
    for (int i = gtid; i < N_NODES; i += nthr) { g_deg[i] = 0; g_fill[i] = 0; }
    for (int i = gtid; i < N_GRAPHS; i += nthr) {
        g_pool[i] = 0.f;
        int a = 0, b = N_NODES;
        while (a < b) { int m = (a + b) >> 1; if (batch[m] < i) a = m + 1; else b = m; }
        int lb = a;
        a = 0; b = N_NODES;
        while (a < b) { int m = (a + b) >> 1; if (batch[m] <= i) a = m + 1; else b = m; }
        g_cnt[i] = (float)(a - lb);
    }
    if (gtid == 0) g_total = 0;
    gbar();

    // ---- P1: in-degree histogram ----
    for (int e = gtid; e < N_EDGES; e += nthr) atomicAdd(&g_deg[dst[e]], 1);
    gbar();

    // ---- P2: CSR row starts. Block-local prefix + one atomic base per block.
    //      (CSR region order across blocks is arbitrary; only contiguity matters.) ----
    {
        int chunk = (N_NODES + gridDim.x - 1) / gridDim.x;
        int lo = blockIdx.x * chunk;
        int hi = lo + chunk; if (hi > N_NODES) hi = N_NODES;
        if (tid == 0) sm.scan.carry = 0;
        __syncthreads();
        if (lo < N_NODES) {
            for (int b0 = lo; b0 < hi; b0 += TPB) {
                int i = b0 + tid;
                int v = (i < hi) ? g_deg[i] : 0;
                sm.scan.vals[tid] = v;
                __syncthreads();
                for (int off = 1; off < TPB; off <<= 1) {
                    int y = (tid >= off) ? sm.scan.vals[tid - off] : 0;
                    __syncthreads();
                    sm.scan.vals[tid] += y;
                    __syncthreads();
                }
                int excl = sm.scan.vals[tid] - v + sm.scan.carry;
                if (i < hi) g_start[i] = excl;
                __syncthreads();
                if (tid == 0) sm.scan.carry += sm.scan.vals[TPB - 1];
                __syncthreads();
            }
        }
        if (tid == 0) {
            int total = (lo < N_NODES) ? sm.scan.carry : 0;
            sm.scan.carry = atomicAdd(&g_total, total);  // reuse as block base
        }
        __syncthreads();
        int base = sm.scan.carry;
        for (int i = lo + tid; i < hi; i += TPB) g_start[i] += base;
    }
    gbar();

    // ---- P3: CSR fill + layer-1 GEMM (independent; no barrier between) ----
    for (int e = gtid; e < N_EDGES; e += nthr) {
        int d = dst[e];
        int pos = g_start[d] + atomicAdd(&g_fill[d], 1);
        g_csr[pos] = src[e];
    }
    gemm_phase<0>(sm, x, W1, nullptr);
    gbar();

    // ---- layers ----
    aggr_phase<false>(nullptr, nullptr, nullptr);
    gbar();
    gemm_phase<1>(sm, nullptr, W2, b1);
    gbar();
    aggr_phase<false>(nullptr, nullptr, nullptr);
    gbar();
    gemm_phase<2>(sm, nullptr, W3, b2);
    gbar();
    aggr_phase<true>(batch, Wl, b3);
    gbar();

    // ---- P9: mean + linear head + sigmoid ----
    for (int g = gtid; g < N_GRAPHS; g += nthr) {
        float c = fmaxf(g_cnt[g], 1.0f);
        float z = g_pool[g] / c + bl[0];
        out[g] = 1.0f / (1.0f + expf(-z));
    }
}

// warmup helper: balanced dummy edges (i % N_NODES) so static-init run is fast
__global__ void k_iota() {
    int i = blockIdx.x * blockDim.x + threadIdx.x;
    if (i < N_EDGES) g_csr[i] = i % N_NODES;
}

// ---------------- static init: occupancy-sized grid + full warmup ----------------
namespace {
int g_grid = 296;
struct CudaWarmup {
    CudaWarmup() {
        cudaFree(0);
        int dev = 0; cudaGetDevice(&dev);
        int sms = 148;
        cudaDeviceGetAttribute(&sms, cudaDevAttrMultiProcessorCount, dev);
        int bps = 1;
        cudaOccupancyMaxActiveBlocksPerMultiprocessor(&bps, k_persist, TPB, 0);
        if (bps < 1) bps = 1;
        g_grid = sms * bps;

        void *pcsr = nullptr, *pacc = nullptr, *pdeg = nullptr;
        cudaGetSymbolAddress(&pcsr, g_csr);
        cudaGetSymbolAddress(&pacc, g_acc);
        cudaGetSymbolAddress(&pdeg, g_deg);
        const int*   ip = (const int*)pcsr;   // iota % N_NODES -> valid node ids
        const int*   bp = (const int*)pdeg;   // after P1, deg==16 < N_GRAPHS: valid pool ids
        const float* fp = (const float*)pacc; // 12.8MB zeros: big enough for x/W/b/Wl/bl

        k_iota<<<(N_EDGES + 255) / 256, 256>>>();
        k_persist<<<g_grid, TPB>>>(fp, ip, ip, bp, fp, fp, fp, fp, fp, fp, fp, fp, (float*)pacc);
        cudaDeviceSynchronize();
    }
};
CudaWarmup g_warmup_instance;
}  // namespace

// ---------------- launch: a single kernel ----------------
extern "C" void kernel_launch(void* const* d_in, const int* in_sizes, int n_in,
                              void* d_out, int out_size) {
    const float* x     = (const float*)d_in[0];
    const int*   ei    = (const int*)d_in[1];    // int32 (JAX x64 disabled)
    const int*   batch = (const int*)d_in[2];
    const float* W1 = (const float*)d_in[3];
    const float* b1 = (const float*)d_in[4];
    const float* W2 = (const float*)d_in[5];
    const float* b2 = (const float*)d_in[6];
    const float* W3 = (const float*)d_in[7];
    const float* b3 = (const float*)d_in[8];
    const float* Wl = (const float*)d_in[9];
    const float* bl = (const float*)d_in[10];
    float* out = (float*)d_out;

    k_persist<<<g_grid, TPB>>>(x, ei, ei + N_EDGES, batch,
                               W1, b1, W2, b2, W3, b3, Wl, bl, out);
}